// round 1
// baseline (speedup 1.0000x reference)
#include <cuda_runtime.h>
#include <cstdint>

// ---------------------------------------------------------------------------
// Problem constants (fixed by the dataset)
// ---------------------------------------------------------------------------
#define NB      512          // batch size
#define FD      256          // feature dim
#define HID     512          // pool hidden dim
#define DOUTC   128          // d_out per half
#define MAXDEG  128
#define NS0     25           // layer-0 fanout (hop 1 uses this)
#define NS1     10           // layer-1 fanout (hop 0 uses this)
#define S1N     (NB * NS1)   // 5120
#define S2N     (S1N * NS0)  // 128000
#define NNODES  100000

// ---------------------------------------------------------------------------
// Device-global scratch (no allocations allowed)
// ---------------------------------------------------------------------------
__device__ float g_P [(size_t)NNODES * HID];   // relu(features @ W_pool0 + b)  ~205 MB
__device__ float g_P1[(size_t)2 * S1N * HID];  // relu(h1 @ W_pool1 + b)        ~21 MB
__device__ float g_h0[2 * NB  * FD];           // layer-0 output for batch nodes
__device__ float g_h1[2 * S1N * FD];           // layer-0 output for hop-1 nodes
__device__ int   g_s1[2 * S1N];
__device__ int   g_s2[2 * S2N];

// ---------------------------------------------------------------------------
// f32x2 packed-FMA helpers (sm_103a; only reachable via PTX)
// ---------------------------------------------------------------------------
__device__ __forceinline__ unsigned long long ffma2(unsigned long long a,
                                                    unsigned long long b,
                                                    unsigned long long c) {
    unsigned long long d;
    asm("fma.rn.f32x2 %0, %1, %2, %3;" : "=l"(d) : "l"(a), "l"(b), "l"(c));
    return d;
}
__device__ __forceinline__ unsigned long long pack2(float lo, float hi) {
    unsigned long long r;
    asm("mov.b64 %0, {%1, %2};" : "=l"(r) : "f"(lo), "f"(hi));
    return r;
}
__device__ __forceinline__ void unpack2(unsigned long long v, float& lo, float& hi) {
    asm("mov.b64 {%0, %1}, %2;" : "=f"(lo), "=f"(hi) : "l"(v));
}

// ---------------------------------------------------------------------------
// Sampling
// ---------------------------------------------------------------------------
__global__ void sample1_kernel(const int* __restrict__ batch1,
                               const int* __restrict__ batch2,
                               const int* __restrict__ adj) {
    int i = blockIdx.x * blockDim.x + threadIdx.x;
    if (i >= 2 * S1N) return;
    int g  = i / S1N;
    int rr = i - g * S1N;
    int b  = rr / NS1;
    int j  = rr - b * NS1;
    const int* bt = g ? batch2 : batch1;
    g_s1[i] = adj[(size_t)bt[b] * MAXDEG + j];
}

__global__ void sample2_kernel(const int* __restrict__ adj) {
    int i = blockIdx.x * blockDim.x + threadIdx.x;
    if (i >= 2 * S2N) return;
    int g  = i / S2N;
    int rr = i - g * S2N;
    int p  = rr / NS0;
    int m  = rr - p * NS0;
    g_s2[i] = adj[(size_t)g_s1[g * S1N + p] * MAXDEG + m];
}

// ---------------------------------------------------------------------------
// C[M,512] = relu(A[M,256] @ W[256,512] + bias[512])
// 64x64 CTA tile, BK=32, 256 threads, 4x4 per thread, f32x2 packed FMAs.
// ---------------------------------------------------------------------------
__global__ __launch_bounds__(256)
void gemm_relu(const float* __restrict__ A, const float* __restrict__ W,
               const float* __restrict__ bias, float* __restrict__ C, int M) {
    __shared__ float As[32][68];   // transposed A tile, padded (272B stride, 16B-aligned)
    __shared__ float Bs[32][64];

    const int tid = threadIdx.x;
    const int tx  = tid & 15;
    const int ty  = tid >> 4;
    const int tx4 = tx * 4;
    const int ty4 = ty * 4;
    const int m0  = blockIdx.y * 64;
    const int n0  = blockIdx.x * 64;

    unsigned long long acc[4][2] = {{0ull, 0ull}, {0ull, 0ull}, {0ull, 0ull}, {0ull, 0ull}};

    for (int kb = 0; kb < FD; kb += 32) {
        // ---- load A tile (transposed into smem) ----
#pragma unroll
        for (int t = 0; t < 2; t++) {
            int f   = tid * 2 + t;            // 0..511
            int row = f >> 3;                 // 0..63
            int c4  = (f & 7) * 4;            // 0..28
            int gr  = m0 + row;
            float4 v = make_float4(0.f, 0.f, 0.f, 0.f);
            if (gr < M) v = *(const float4*)&A[(size_t)gr * FD + kb + c4];
            As[c4 + 0][row] = v.x;
            As[c4 + 1][row] = v.y;
            As[c4 + 2][row] = v.z;
            As[c4 + 3][row] = v.w;
        }
        // ---- load B tile ----
#pragma unroll
        for (int t = 0; t < 2; t++) {
            int f   = tid * 2 + t;            // 0..511
            int row = f >> 4;                 // 0..31
            int c4  = (f & 15) * 4;           // 0..60
            *(float4*)&Bs[row][c4] = *(const float4*)&W[(size_t)(kb + row) * HID + n0 + c4];
        }
        __syncthreads();

#pragma unroll
        for (int kk = 0; kk < 32; kk++) {
            float4 av = *(const float4*)&As[kk][ty4];
            ulonglong2 bv = *(const ulonglong2*)&Bs[kk][tx4];
            unsigned long long a;
            a = pack2(av.x, av.x); acc[0][0] = ffma2(a, bv.x, acc[0][0]); acc[0][1] = ffma2(a, bv.y, acc[0][1]);
            a = pack2(av.y, av.y); acc[1][0] = ffma2(a, bv.x, acc[1][0]); acc[1][1] = ffma2(a, bv.y, acc[1][1]);
            a = pack2(av.z, av.z); acc[2][0] = ffma2(a, bv.x, acc[2][0]); acc[2][1] = ffma2(a, bv.y, acc[2][1]);
            a = pack2(av.w, av.w); acc[3][0] = ffma2(a, bv.x, acc[3][0]); acc[3][1] = ffma2(a, bv.y, acc[3][1]);
        }
        __syncthreads();
    }

    float4 bvals = *(const float4*)&bias[n0 + tx4];
#pragma unroll
    for (int i = 0; i < 4; i++) {
        int row = m0 + ty4 + i;
        if (row >= M) continue;
        float* cp = &C[(size_t)row * HID + n0 + tx4];
        float lo, hi;
        unpack2(acc[i][0], lo, hi);
        cp[0] = fmaxf(lo + bvals.x, 0.f);
        cp[1] = fmaxf(hi + bvals.y, 0.f);
        unpack2(acc[i][1], lo, hi);
        cp[2] = fmaxf(lo + bvals.z, 0.f);
        cp[3] = fmaxf(hi + bvals.w, 0.f);
    }
}

// ---------------------------------------------------------------------------
// Layer-0 aggregate: one CTA per output row.
//   maxh = max_k P[nb_k]            (gather-max, P already relu'd and >= 0)
//   out  = relu([self@Wself , maxh@Wneigh])
// ---------------------------------------------------------------------------
__global__ __launch_bounds__(256)
void agg_layer0(const int* __restrict__ selfIds, const int* __restrict__ neighIds,
                int K, const float* __restrict__ features,
                const float* __restrict__ Wself, const float* __restrict__ Wneigh,
                float* __restrict__ out) {
    __shared__ float maxh[HID];
    __shared__ float selff[FD];
    __shared__ int   nb[32];
    __shared__ int   sid_s;

    const int tid = threadIdx.x;
    const int r   = blockIdx.x;

    if (tid < K) nb[tid] = neighIds[(size_t)r * K + tid];
    if (tid == 0) sid_s = selfIds[r];
    __syncthreads();

    const int sid = sid_s;
#pragma unroll
    for (int h = tid; h < HID; h += 256) {
        float m = 0.f;                              // P >= 0 (post-relu)
        for (int k = 0; k < K; k++)
            m = fmaxf(m, g_P[(size_t)nb[k] * HID + h]);
        maxh[h] = m;
    }
    selff[tid] = features[(size_t)sid * FD + tid];  // tid < 256 == FD
    __syncthreads();

    float acc = 0.f;
    if (tid < DOUTC) {
#pragma unroll 8
        for (int d = 0; d < FD; d++) acc += selff[d] * Wself[d * DOUTC + tid];
        out[(size_t)r * FD + tid] = fmaxf(acc, 0.f);
    } else {
        const int c = tid - DOUTC;
#pragma unroll 8
        for (int d = 0; d < HID; d++) acc += maxh[d] * Wneigh[d * DOUTC + c];
        out[(size_t)r * FD + DOUTC + c] = fmaxf(acc, 0.f);
    }
}

// ---------------------------------------------------------------------------
// Layer-1 aggregate + row L2-normalize. One CTA per final output row (1024).
// ---------------------------------------------------------------------------
__global__ __launch_bounds__(256)
void agg_layer1(const float* __restrict__ Wself, const float* __restrict__ Wneigh,
                float* __restrict__ out) {
    __shared__ float maxh[HID];
    __shared__ float selff[FD];
    __shared__ float o[FD];
    __shared__ float red[8];

    const int tid = threadIdx.x;
    const int r   = blockIdx.x;          // 0..1023
    const int g   = r >> 9;
    const int rr  = r & 511;
    const int nbase = g * S1N + rr * NS1;

#pragma unroll
    for (int h = tid; h < HID; h += 256) {
        float m = 0.f;                   // P1 >= 0 (post-relu)
#pragma unroll
        for (int k = 0; k < NS1; k++)
            m = fmaxf(m, g_P1[(size_t)(nbase + k) * HID + h]);
        maxh[h] = m;
    }
    selff[tid] = g_h0[(size_t)r * FD + tid];
    __syncthreads();

    float v = 0.f;
    if (tid < DOUTC) {
#pragma unroll 8
        for (int d = 0; d < FD; d++) v += selff[d] * Wself[d * DOUTC + tid];
        o[tid] = v;
    } else {
        const int c = tid - DOUTC;
#pragma unroll 8
        for (int d = 0; d < HID; d++) v += maxh[d] * Wneigh[d * DOUTC + c];
        o[DOUTC + c] = v;
    }
    __syncthreads();

    float x  = o[tid];
    float ss = x * x;
#pragma unroll
    for (int off = 16; off > 0; off >>= 1)
        ss += __shfl_xor_sync(0xffffffffu, ss, off);
    if ((tid & 31) == 0) red[tid >> 5] = ss;
    __syncthreads();
    if (tid < 8) {
        float s2 = red[tid];
#pragma unroll
        for (int off = 4; off > 0; off >>= 1)
            s2 += __shfl_xor_sync(0xffu, s2, off);
        if (tid == 0) red[0] = s2;
    }
    __syncthreads();

    float norm  = sqrtf(red[0]);
    float scale = 1.f / fmaxf(norm, 1e-12f);
    out[(size_t)r * FD + tid] = x * scale;
}

// ---------------------------------------------------------------------------
// Launch
// ---------------------------------------------------------------------------
extern "C" void kernel_launch(void* const* d_in, const int* in_sizes, int n_in,
                              void* d_out, int out_size) {
    const int*   batch1   = (const int*)d_in[0];
    const int*   batch2   = (const int*)d_in[1];
    const float* features = (const float*)d_in[2];
    const int*   adj      = (const int*)d_in[3];
    const float* W_pool0  = (const float*)d_in[4];
    const float* b_pool0  = (const float*)d_in[5];
    const float* W_neigh0 = (const float*)d_in[6];
    const float* W_self0  = (const float*)d_in[7];
    const float* W_pool1  = (const float*)d_in[8];
    const float* b_pool1  = (const float*)d_in[9];
    const float* W_neigh1 = (const float*)d_in[10];
    const float* W_self1  = (const float*)d_in[11];
    float* out = (float*)d_out;

    const int nnodes = in_sizes[2] / FD;

    float *pP, *pP1, *ph0, *ph1;
    int   *ps1, *ps2;
    cudaGetSymbolAddress((void**)&pP,  g_P);
    cudaGetSymbolAddress((void**)&pP1, g_P1);
    cudaGetSymbolAddress((void**)&ph0, g_h0);
    cudaGetSymbolAddress((void**)&ph1, g_h1);
    cudaGetSymbolAddress((void**)&ps1, g_s1);
    cudaGetSymbolAddress((void**)&ps2, g_s2);

    // 1) neighbor sampling
    sample1_kernel<<<(2 * S1N + 255) / 256, 256>>>(batch1, batch2, adj);
    sample2_kernel<<<(2 * S2N + 255) / 256, 256>>>(adj);

    // 2) P = relu(features @ W_pool0 + b_pool0) for ALL nodes (dense GEMM)
    gemm_relu<<<dim3(HID / 64, (nnodes + 63) / 64), 256>>>(features, W_pool0, b_pool0, pP, nnodes);

    // 3) layer-0 aggregation (hop 0: batch rows; hop 1: s1 rows), both batches
    agg_layer0<<<NB,  256>>>(batch1,      ps1,       NS1, features, W_self0, W_neigh0, ph0);
    agg_layer0<<<NB,  256>>>(batch2,      ps1 + S1N, NS1, features, W_self0, W_neigh0, ph0 + NB * FD);
    agg_layer0<<<S1N, 256>>>(ps1,         ps2,       NS0, features, W_self0, W_neigh0, ph1);
    agg_layer0<<<S1N, 256>>>(ps1 + S1N,   ps2 + S2N, NS0, features, W_self0, W_neigh0, ph1 + S1N * FD);

    // 4) P1 = relu(h1 @ W_pool1 + b_pool1) for all 10240 hop-1 rows
    gemm_relu<<<dim3(HID / 64, (2 * S1N) / 64), 256>>>(ph1, W_pool1, b_pool1, pP1, 2 * S1N);

    // 5) layer-1 aggregation + L2 normalize -> d_out (o1 rows then o2 rows)
    agg_layer1<<<2 * NB, 256>>>(W_self1, W_neigh1, out);
}

// round 17
// speedup vs baseline: 1.8023x; 1.8023x over previous
#include <cuda_runtime.h>
#include <cuda_bf16.h>
#include <cstdint>

// ---------------------------------------------------------------------------
// Problem constants
// ---------------------------------------------------------------------------
#define NB      512
#define FD      256
#define HID     512
#define DOUTC   128
#define MAXDEG  128
#define NS0     25
#define NS1     10
#define S1N     (NB * NS1)    // 5120
#define S2N     (S1N * NS0)   // 128000
#define MPAD    100096        // 782 * 128
#define H1ROWS  (2 * S1N)     // 10240

// ---------------------------------------------------------------------------
// Device-global scratch
// ---------------------------------------------------------------------------
__device__ __align__(256) float g_P [(size_t)100000 * HID];
__device__ __align__(256) float g_P1[(size_t)H1ROWS * HID];
__device__ __align__(256) float g_h0[2 * NB * FD];
__device__ __align__(256) __nv_bfloat16 g_Ah[(size_t)MPAD * FD];
__device__ __align__(256) __nv_bfloat16 g_Al[(size_t)MPAD * FD];
__device__ __align__(256) __nv_bfloat16 g_Hh[(size_t)H1ROWS * FD];
__device__ __align__(256) __nv_bfloat16 g_Hl[(size_t)H1ROWS * FD];
__device__ __align__(256) __nv_bfloat16 g_W0h[HID * FD];   // transposed [n][k]
__device__ __align__(256) __nv_bfloat16 g_W0l[HID * FD];
__device__ __align__(256) __nv_bfloat16 g_W1h[HID * FD];
__device__ __align__(256) __nv_bfloat16 g_W1l[HID * FD];
__device__ int g_s1[2 * S1N];
__device__ int g_s2[2 * S2N];
__device__ int g_self0[2 * NB];

// ---------------------------------------------------------------------------
// PTX helpers — ONLY family-agnostic instructions (sm_80/75 era):
// cp.async, ldmatrix, mma.sync. No tcgen05/TMEM/mbarrier.
// ---------------------------------------------------------------------------
__device__ __forceinline__ uint32_t smem_u32(const void* p) {
    uint32_t a;
    asm("{ .reg .u64 t; cvta.to.shared.u64 t, %1; cvt.u32.u64 %0, t; }" : "=r"(a) : "l"(p));
    return a;
}
__device__ __forceinline__ void cpa16(uint32_t dst, const void* src) {
    asm volatile("cp.async.cg.shared.global [%0], [%1], 16;" :: "r"(dst), "l"(src));
}
#define CP_COMMIT() asm volatile("cp.async.commit_group;" ::: "memory")
#define CP_WAIT1()  asm volatile("cp.async.wait_group 1;" ::: "memory")
#define CP_WAIT0()  asm volatile("cp.async.wait_group 0;" ::: "memory")

__device__ __forceinline__ void ldsm4(uint32_t& r0, uint32_t& r1, uint32_t& r2, uint32_t& r3,
                                      uint32_t a) {
    asm volatile("ldmatrix.sync.aligned.m8n8.x4.shared.b16 {%0,%1,%2,%3}, [%4];"
                 : "=r"(r0), "=r"(r1), "=r"(r2), "=r"(r3) : "r"(a));
}
__device__ __forceinline__ void mma16816(float* c, const uint32_t* a, const uint32_t* b) {
    asm volatile(
        "mma.sync.aligned.m16n8k16.row.col.f32.bf16.bf16.f32 "
        "{%0,%1,%2,%3}, {%4,%5,%6,%7}, {%8,%9}, {%0,%1,%2,%3};"
        : "+f"(c[0]), "+f"(c[1]), "+f"(c[2]), "+f"(c[3])
        : "r"(a[0]), "r"(a[1]), "r"(a[2]), "r"(a[3]), "r"(b[0]), "r"(b[1]));
}

// ---------------------------------------------------------------------------
// Sampling
// ---------------------------------------------------------------------------
__global__ void sample1_kernel(const int* __restrict__ batch1,
                               const int* __restrict__ batch2,
                               const int* __restrict__ adj) {
    int i = blockIdx.x * blockDim.x + threadIdx.x;
    if (i < 2 * S1N) {
        int g  = i / S1N;
        int rr = i - g * S1N;
        int b  = rr / NS1;
        int j  = rr - b * NS1;
        const int* bt = g ? batch2 : batch1;
        g_s1[i] = adj[(size_t)bt[b] * MAXDEG + j];
    } else if (i < 2 * S1N + 2 * NB) {
        int t = i - 2 * S1N;
        g_self0[t] = (t < NB) ? batch1[t] : batch2[t - NB];
    }
}

__global__ void sample2_kernel(const int* __restrict__ adj) {
    int i = blockIdx.x * blockDim.x + threadIdx.x;
    if (i >= 2 * S2N) return;
    int p = i / NS0;
    int m = i - p * NS0;
    g_s2[i] = adj[(size_t)g_s1[p] * MAXDEG + m];
}

// ---------------------------------------------------------------------------
// Precision-split conversions
// ---------------------------------------------------------------------------
__global__ void convert_feat(const float4* __restrict__ in,
                             __nv_bfloat162* __restrict__ h,
                             __nv_bfloat162* __restrict__ l, int n4) {
    int i = blockIdx.x * blockDim.x + threadIdx.x;
    if (i >= n4) return;
    float4 v = in[i];
    __nv_bfloat16 a = __float2bfloat16(v.x), b = __float2bfloat16(v.y);
    __nv_bfloat16 c = __float2bfloat16(v.z), d = __float2bfloat16(v.w);
    h[2 * i]     = __halves2bfloat162(a, b);
    h[2 * i + 1] = __halves2bfloat162(c, d);
    l[2 * i]     = __halves2bfloat162(__float2bfloat16(v.x - __bfloat162float(a)),
                                      __float2bfloat16(v.y - __bfloat162float(b)));
    l[2 * i + 1] = __halves2bfloat162(__float2bfloat16(v.z - __bfloat162float(c)),
                                      __float2bfloat16(v.w - __bfloat162float(d)));
}

// Both pool weights [256,512] fp32 -> transposed [512,256] bf16 hi/lo.
__global__ void convert_w2(const float* __restrict__ W0, const float* __restrict__ W1) {
    int idx = blockIdx.x * blockDim.x + threadIdx.x;       // < 2*512*256
    int which = idx >= HID * FD;
    int li = idx - which * HID * FD;
    int n = li >> 8, k = li & 255;
    const float* W = which ? W1 : W0;
    float x = W[k * HID + n];
    __nv_bfloat16 xh = __float2bfloat16(x);
    (which ? g_W1h : g_W0h)[li] = xh;
    (which ? g_W1l : g_W0l)[li] = __float2bfloat16(x - __bfloat162float(xh));
}

// ---------------------------------------------------------------------------
// mma.sync GEMM: C[M,512] = relu(A[M,256] @ W[256,512] + bias)
// A: bf16 hi/lo [M,256] row-major. W: transposed [512,256] bf16 hi/lo (n-major).
// CTA tile 128x128, 8 warps (warp tile 64x32), K chunks of 32, double-buffered
// cp.async. SMEM rows padded to 80B (stride 80 mod 128 hits all 8 16B-banks ->
// conflict-free ldmatrix). 3-term split: Ah*Bh + Ah*Bl + Al*Bh.
// ---------------------------------------------------------------------------
#define KCHUNK 32
#define NCHNK  (FD / KCHUNK)    // 8
#define RS     80               // padded SMEM row stride (bytes) for 64B rows
#define TSZ    (128 * RS)       // 10240 bytes per tensor per stage
#define STAGE  (4 * TSZ)        // Ah | Al | Bh | Bl
#define HDR    1024             // bias stage (512B used)
#define GSMEM  (HDR + 2 * STAGE)  // 82944

__device__ __forceinline__ void load_chunk(uint32_t stg, int kb, int m0, int n0,
        const __nv_bfloat16* __restrict__ Ah, const __nv_bfloat16* __restrict__ Al,
        const __nv_bfloat16* __restrict__ Bh, const __nv_bfloat16* __restrict__ Bl,
        int tid) {
#pragma unroll
    for (int i = 0; i < 8; i++) {
        int flat   = tid + i * 256;              // 0..2047
        int seg    = flat & 3;                   // 16B segment in 64B row
        int row    = (flat >> 2) & 127;
        int tensor = flat >> 9;                  // 0..3
        const __nv_bfloat16* base = (tensor == 0) ? Ah : (tensor == 1) ? Al
                                  : (tensor == 2) ? Bh : Bl;
        int grow = ((tensor < 2) ? m0 : n0) + row;
        const char* src = (const char*)(base + (size_t)grow * FD + kb) + seg * 16;
        cpa16(stg + tensor * TSZ + (uint32_t)(row * RS + seg * 16), src);
    }
}

__global__ __launch_bounds__(256, 1)
void gemm_mma(const __nv_bfloat16* __restrict__ Ah, const __nv_bfloat16* __restrict__ Al,
              const __nv_bfloat16* __restrict__ Bh, const __nv_bfloat16* __restrict__ Bl,
              const float* __restrict__ bias, float* __restrict__ C, int Mreal) {
    extern __shared__ char smem[];
    uint32_t sb = smem_u32(smem);
    const int tid  = threadIdx.x;
    const int lane = tid & 31;
    const int wid  = tid >> 5;
    const int wm   = wid & 1;         // 2 warps over M (64 each)
    const int wn   = wid >> 1;        // 4 warps over N (32 each)
    const int m0   = blockIdx.y * 128;
    const int n0   = blockIdx.x * 128;
    const int q    = lane >> 3;       // ldmatrix sub-matrix id
    const int rr   = lane & 7;

    float* biass = (float*)smem;
    if (tid < 128) biass[tid] = bias[n0 + tid];

    float acc[4][4][4];
#pragma unroll
    for (int a = 0; a < 4; a++)
#pragma unroll
        for (int b = 0; b < 4; b++)
#pragma unroll
            for (int c = 0; c < 4; c++) acc[a][b][c] = 0.f;

    const uint32_t st0 = sb + HDR;
    const uint32_t st1 = st0 + STAGE;

    load_chunk(st0, 0,      m0, n0, Ah, Al, Bh, Bl, tid); CP_COMMIT();
    load_chunk(st1, KCHUNK, m0, n0, Ah, Al, Bh, Bl, tid); CP_COMMIT();

    for (int c = 0; c < NCHNK; c++) {
        const uint32_t stg = (c & 1) ? st1 : st0;
        if (c < NCHNK - 1) { CP_WAIT1(); } else { CP_WAIT0(); }
        __syncthreads();

#pragma unroll
        for (int s = 0; s < 2; s++) {           // two k16 steps per 32-chunk
            const int k0 = s * 16;
            // B fragments: 4 n8 pieces (h and l)
            uint32_t bh[8], bl[8];
#pragma unroll
            for (int bn = 0; bn < 2; bn++) {
                uint32_t boff = (uint32_t)((wn * 32 + bn * 16 + (q >> 1) * 8 + rr) * RS
                                           + (k0 + (q & 1) * 8) * 2);
                ldsm4(bh[4 * bn], bh[4 * bn + 1], bh[4 * bn + 2], bh[4 * bn + 3],
                      stg + 2 * TSZ + boff);
                ldsm4(bl[4 * bn], bl[4 * bn + 1], bl[4 * bn + 2], bl[4 * bn + 3],
                      stg + 3 * TSZ + boff);
            }
#pragma unroll
            for (int tm = 0; tm < 4; tm++) {
                uint32_t aoff = (uint32_t)((wm * 64 + tm * 16 + (q & 1) * 8 + rr) * RS
                                           + (k0 + (q >> 1) * 8) * 2);
                uint32_t ah[4], al[4];
                ldsm4(ah[0], ah[1], ah[2], ah[3], stg + aoff);
                ldsm4(al[0], al[1], al[2], al[3], stg + TSZ + aoff);
#pragma unroll
                for (int j = 0; j < 4; j++) {   // n8 piece j; frag = {b[2j], b[2j+1]}
                    mma16816(acc[tm][j], ah, &bh[2 * j]);
                    mma16816(acc[tm][j], ah, &bl[2 * j]);
                    mma16816(acc[tm][j], al, &bh[2 * j]);
                }
            }
        }
        __syncthreads();
        if (c + 2 < NCHNK) {
            load_chunk(stg, (c + 2) * KCHUNK, m0, n0, Ah, Al, Bh, Bl, tid);
            CP_COMMIT();
        }
    }

    // Epilogue: c-frag rows lane/4 (+8), cols (lane%4)*2 (+1)
    const int r0q = lane >> 2;
    const int cq  = (lane & 3) * 2;
#pragma unroll
    for (int tm = 0; tm < 4; tm++) {
        const int mrow = m0 + wm * 64 + tm * 16 + r0q;
#pragma unroll
        for (int j = 0; j < 4; j++) {
            const int coll = wn * 32 + j * 8 + cq;
            const float bx = biass[coll], by = biass[coll + 1];
            if (mrow < Mreal) {
                float2 v;
                v.x = fmaxf(acc[tm][j][0] + bx, 0.f);
                v.y = fmaxf(acc[tm][j][1] + by, 0.f);
                *(float2*)&C[(size_t)mrow * HID + n0 + coll] = v;
            }
            if (mrow + 8 < Mreal) {
                float2 v;
                v.x = fmaxf(acc[tm][j][2] + bx, 0.f);
                v.y = fmaxf(acc[tm][j][3] + by, 0.f);
                *(float2*)&C[(size_t)(mrow + 8) * HID + n0 + coll] = v;
            }
        }
    }
}

// ---------------------------------------------------------------------------
// Layer-0 aggregate, R rows per CTA, compile-time K.
// ---------------------------------------------------------------------------
template<int K, int R, bool WB16>
__global__ __launch_bounds__(256)
void agg0(const int* __restrict__ selfIds, const int* __restrict__ neighIds,
          const float* __restrict__ features,
          const float* __restrict__ Wself, const float* __restrict__ Wneigh,
          float* __restrict__ outF, __nv_bfloat16* __restrict__ outH,
          __nv_bfloat16* __restrict__ outL) {
    __shared__ float maxh[R][HID];
    __shared__ float selff[R][FD];
    __shared__ int   nb[R][K];
    __shared__ int   sid[R];

    const int tid = threadIdx.x;
    const int r0  = blockIdx.x * R;

    if (tid < R * K) nb[tid / K][tid % K] = neighIds[(size_t)r0 * K + tid];
    if (tid < R)     sid[tid] = selfIds[r0 + tid];
    __syncthreads();

    const float2* P2 = (const float2*)g_P;
#pragma unroll
    for (int r = 0; r < R; r++) {
        float2 m = make_float2(0.f, 0.f);   // P >= 0 (post-relu)
#pragma unroll
        for (int k = 0; k < K; k++) {
            float2 v = P2[(size_t)nb[r][k] * (HID / 2) + tid];
            m.x = fmaxf(m.x, v.x);
            m.y = fmaxf(m.y, v.y);
        }
        *(float2*)&maxh[r][tid * 2] = m;
    }
#pragma unroll
    for (int r = 0; r < R; r++)
        selff[r][tid] = features[(size_t)sid[r] * FD + tid];
    __syncthreads();

    float acc[R];
#pragma unroll
    for (int r = 0; r < R; r++) acc[r] = 0.f;

    if (tid < DOUTC) {
#pragma unroll 4
        for (int d = 0; d < FD; d++) {
            float w = Wself[d * DOUTC + tid];
#pragma unroll
            for (int r = 0; r < R; r++) acc[r] += selff[r][d] * w;
        }
    } else {
        const int c = tid - DOUTC;
#pragma unroll 4
        for (int d = 0; d < HID; d++) {
            float w = Wneigh[d * DOUTC + c];
#pragma unroll
            for (int r = 0; r < R; r++) acc[r] += maxh[r][d] * w;
        }
    }

#pragma unroll
    for (int r = 0; r < R; r++) {
        float val = fmaxf(acc[r], 0.f);
        size_t o = (size_t)(r0 + r) * FD + tid;
        if (WB16) {
            __nv_bfloat16 vh = __float2bfloat16(val);
            outH[o] = vh;
            outL[o] = __float2bfloat16(val - __bfloat162float(vh));
        } else {
            outF[o] = val;
        }
    }
}

// ---------------------------------------------------------------------------
// Layer-1 aggregate + L2 normalize. One CTA per final row (1024).
// ---------------------------------------------------------------------------
__global__ __launch_bounds__(256)
void agg_layer1(const float* __restrict__ Wself, const float* __restrict__ Wneigh,
                float* __restrict__ out) {
    __shared__ float maxh[HID];
    __shared__ float selff[FD];
    __shared__ float o[FD];
    __shared__ float red[8];

    const int tid = threadIdx.x;
    const int r   = blockIdx.x;          // 0..1023
    const int nbase = r * NS1;

#pragma unroll
    for (int h = tid; h < HID; h += 256) {
        float m = 0.f;
#pragma unroll
        for (int k = 0; k < NS1; k++)
            m = fmaxf(m, g_P1[(size_t)(nbase + k) * HID + h]);
        maxh[h] = m;
    }
    selff[tid] = g_h0[(size_t)r * FD + tid];
    __syncthreads();

    float v = 0.f;
    if (tid < DOUTC) {
#pragma unroll 8
        for (int d = 0; d < FD; d++) v += selff[d] * Wself[d * DOUTC + tid];
        o[tid] = v;
    } else {
        const int c = tid - DOUTC;
#pragma unroll 8
        for (int d = 0; d < HID; d++) v += maxh[d] * Wneigh[d * DOUTC + c];
        o[DOUTC + c] = v;
    }
    __syncthreads();

    float x  = o[tid];
    float ss = x * x;
#pragma unroll
    for (int off = 16; off > 0; off >>= 1)
        ss += __shfl_xor_sync(0xffffffffu, ss, off);
    if ((tid & 31) == 0) red[tid >> 5] = ss;
    __syncthreads();
    if (tid < 8) {
        float s2 = red[tid];
#pragma unroll
        for (int off = 4; off > 0; off >>= 1)
            s2 += __shfl_xor_sync(0xffu, s2, off);
        if (tid == 0) red[0] = s2;
    }
    __syncthreads();

    float scale = 1.f / fmaxf(sqrtf(red[0]), 1e-12f);
    out[(size_t)r * FD + tid] = x * scale;
}

// ---------------------------------------------------------------------------
// Launch
// ---------------------------------------------------------------------------
extern "C" void kernel_launch(void* const* d_in, const int* in_sizes, int n_in,
                              void* d_out, int out_size) {
    const int*   batch1   = (const int*)d_in[0];
    const int*   batch2   = (const int*)d_in[1];
    const float* features = (const float*)d_in[2];
    const int*   adj      = (const int*)d_in[3];
    const float* W_pool0  = (const float*)d_in[4];
    const float* b_pool0  = (const float*)d_in[5];
    const float* W_neigh0 = (const float*)d_in[6];
    const float* W_self0  = (const float*)d_in[7];
    const float* W_pool1  = (const float*)d_in[8];
    const float* b_pool1  = (const float*)d_in[9];
    const float* W_neigh1 = (const float*)d_in[10];
    const float* W_self1  = (const float*)d_in[11];
    float* out = (float*)d_out;

    const int nnodes = in_sizes[2] / FD;

    float *pP, *pP1, *ph0;
    __nv_bfloat16 *pAh, *pAl, *pHh, *pHl, *pW0h, *pW0l, *pW1h, *pW1l;
    int *ps1, *ps2, *pself0;
    cudaGetSymbolAddress((void**)&pP,   g_P);
    cudaGetSymbolAddress((void**)&pP1,  g_P1);
    cudaGetSymbolAddress((void**)&ph0,  g_h0);
    cudaGetSymbolAddress((void**)&pAh,  g_Ah);
    cudaGetSymbolAddress((void**)&pAl,  g_Al);
    cudaGetSymbolAddress((void**)&pHh,  g_Hh);
    cudaGetSymbolAddress((void**)&pHl,  g_Hl);
    cudaGetSymbolAddress((void**)&pW0h, g_W0h);
    cudaGetSymbolAddress((void**)&pW0l, g_W0l);
    cudaGetSymbolAddress((void**)&pW1h, g_W1h);
    cudaGetSymbolAddress((void**)&pW1l, g_W1l);
    cudaGetSymbolAddress((void**)&ps1,  g_s1);
    cudaGetSymbolAddress((void**)&ps2,  g_s2);
    cudaGetSymbolAddress((void**)&pself0, g_self0);

    cudaFuncSetAttribute(gemm_mma, cudaFuncAttributeMaxDynamicSharedMemorySize, GSMEM);

    // 1) sampling
    sample1_kernel<<<(2 * S1N + 2 * NB + 255) / 256, 256>>>(batch1, batch2, adj);
    sample2_kernel<<<(2 * S2N + 255) / 256, 256>>>(adj);

    // 2) precision-split conversions
    const int n4 = nnodes * FD / 4;
    convert_feat<<<(n4 + 255) / 256, 256>>>((const float4*)features,
                                            (__nv_bfloat162*)pAh, (__nv_bfloat162*)pAl, n4);
    convert_w2<<<(2 * HID * FD) / 256, 256>>>(W_pool0, W_pool1);

    // 3) P = relu(features @ W_pool0 + b) for all nodes  (mma.sync / HMMA)
    const int mtiles = (nnodes + 127) / 128;
    gemm_mma<<<dim3(HID / 128, mtiles), 256, GSMEM>>>(pAh, pAl, pW0h, pW0l,
                                                      b_pool0, pP, nnodes);

    // 4) layer-0 aggregation (hop0 -> fp32 h0; hop1 -> bf16 splits for pool1)
    agg0<NS1, 4, false><<<(2 * NB) / 4, 256>>>(pself0, ps1, features, W_self0, W_neigh0,
                                               ph0, nullptr, nullptr);
    agg0<NS0, 4, true><<<H1ROWS / 4, 256>>>(ps1, ps2, features, W_self0, W_neigh0,
                                            nullptr, pHh, pHl);

    // 5) P1 = relu(h1 @ W_pool1 + b)  (mma.sync)
    gemm_mma<<<dim3(HID / 128, H1ROWS / 128), 256, GSMEM>>>(pHh, pHl, pW1h, pW1l,
                                                            b_pool1, pP1, H1ROWS);

    // 6) layer-1 aggregation + L2 normalize
    agg_layer1<<<2 * NB, 256>>>(W_self1, W_neigh1, out);
}